// round 1
// baseline (speedup 1.0000x reference)
#include <cuda_runtime.h>
#include <math.h>

#define NH   3
#define D    256
#define E    768
#define B_   8
#define N_   2048

#define QKV_STRIDE (B_*NH*N_*D)   /* 12,582,912 floats per tensor */

// Scratch (allocation-guard-safe): Q/K/V [qkv][b][h][n][d], attn concat [b][n][768]
__device__ float g_QKV[3LL * QKV_STRIDE];
__device__ float g_att[(long long)B_ * N_ * (NH * D)];

// ---------------------------------------------------------------------------
// Kernel 1: QKV projection.  out[b][h][n][d] = x[b][n][:] @ W[h][:,d] + bias
// 128x128 tile, 8x8 micro-tile, K-step 8.  grid (2, 128, 9)
// ---------------------------------------------------------------------------
__global__ void __launch_bounds__(256) qkv_gemm_kernel(
    const float* __restrict__ x,
    const float* __restrict__ Wq, const float* __restrict__ bq,
    const float* __restrict__ Wk, const float* __restrict__ bk,
    const float* __restrict__ Wv, const float* __restrict__ bv)
{
    __shared__ float As[8][128];
    __shared__ float Bs[8][128];

    const int z = blockIdx.z;
    const int qkv = z / 3, h = z - qkv * 3;
    const float* W;
    const float* bias;
    if (qkv == 0)      { W = Wq; bias = bq; }
    else if (qkv == 1) { W = Wk; bias = bk; }
    else               { W = Wv; bias = bv; }
    W    += h * E * D;
    bias += h * D;
    float* out = g_QKV + (long long)qkv * QKV_STRIDE;

    const int m0 = blockIdx.y * 128;
    const int n0 = blockIdx.x * 128;
    const int tid = threadIdx.x;
    const int tx = tid & 15, ty = tid >> 4;
    const int arow = tid >> 1, ak = (tid & 1) << 2;
    const int brow = tid >> 5, bn = (tid & 31) << 2;

    const float* Aptr = x + (m0 + arow) * E + ak;
    const float* Bptr = W + brow * D + n0 + bn;

    float c[8][8];
#pragma unroll
    for (int i = 0; i < 8; i++)
#pragma unroll
        for (int j = 0; j < 8; j++) c[i][j] = 0.f;

    for (int k0 = 0; k0 < E; k0 += 8) {
        float4 av  = *(const float4*)(Aptr + k0);
        float4 bv4 = *(const float4*)(Bptr + k0 * D);
        __syncthreads();
        As[ak + 0][arow] = av.x;
        As[ak + 1][arow] = av.y;
        As[ak + 2][arow] = av.z;
        As[ak + 3][arow] = av.w;
        *(float4*)&Bs[brow][bn] = bv4;
        __syncthreads();
#pragma unroll
        for (int kk = 0; kk < 8; kk++) {
            float a[8], b[8];
            *(float4*)&a[0] = *(float4*)&As[kk][ty * 8];
            *(float4*)&a[4] = *(float4*)&As[kk][ty * 8 + 4];
            *(float4*)&b[0] = *(float4*)&Bs[kk][tx * 8];
            *(float4*)&b[4] = *(float4*)&Bs[kk][tx * 8 + 4];
#pragma unroll
            for (int i = 0; i < 8; i++)
#pragma unroll
                for (int j = 0; j < 8; j++)
                    c[i][j] += a[i] * b[j];
        }
    }

    float bias8[8];
    *(float4*)&bias8[0] = *(const float4*)&bias[n0 + tx * 8];
    *(float4*)&bias8[4] = *(const float4*)&bias[n0 + tx * 8 + 4];

#pragma unroll
    for (int i = 0; i < 8; i++) {
        int m  = m0 + ty * 8 + i;
        int bb = m >> 11;          // / 2048
        int nn = m & (N_ - 1);
        float* orow = out + ((long long)((bb * NH + h) * N_ + nn)) * D + n0 + tx * 8;
        float4 o0, o1;
        o0.x = c[i][0] + bias8[0]; o0.y = c[i][1] + bias8[1];
        o0.z = c[i][2] + bias8[2]; o0.w = c[i][3] + bias8[3];
        o1.x = c[i][4] + bias8[4]; o1.y = c[i][5] + bias8[5];
        o1.z = c[i][6] + bias8[6]; o1.w = c[i][7] + bias8[7];
        *(float4*)&orow[0] = o0;
        *(float4*)&orow[4] = o1;
    }
}

// ---------------------------------------------------------------------------
// Kernel 2: flash attention, fp32, full softmax over N=2048.
// 1 CTA per (b, h, 64-query tile). grid (32, 3, 8), 256 thr, dyn smem 214016 B.
// Q/K smem rows use a 16B-granular XOR swizzle to avoid bank conflicts in the
// row-major-dot access pattern.
// ---------------------------------------------------------------------------
#define ATTN_SMEM_FLOATS (3 * 64 * 256 + 64 * 65 + 192)
#define ATTN_SMEM_BYTES  (ATTN_SMEM_FLOATS * 4)

__global__ void __launch_bounds__(256, 1) attn_kernel()
{
    extern __shared__ float sm[];
    float* Qs  = sm;                  // [64][256] swizzled
    float* Ks  = sm + 16384;          // [64][256] swizzled
    float* Vs  = sm + 32768;          // [64][256] plain
    float* Ps  = sm + 49152;          // [64][65]  padded
    float* m_s = sm + 53312;          // [64]
    float* l_s = sm + 53376;          // [64]
    float* f_s = sm + 53440;          // [64]

    const int b  = blockIdx.z;
    const int h  = blockIdx.y;
    const int q0 = blockIdx.x * 64;
    const int tid = threadIdx.x;
    const int tx = tid & 15, ty = tid >> 4;
    const int r0 = ty * 4;            // query rows owned (4)
    const int c0 = tx * 4;            // key cols owned in S (4)

    const float* Qg    = g_QKV + ((long long)((b * NH + h) * N_ + q0)) * D;
    const float* Kbase = g_QKV + (long long)QKV_STRIDE     + ((long long)((b * NH + h) * N_)) * D;
    const float* Vbase = g_QKV + 2LL * QKV_STRIDE          + ((long long)((b * NH + h) * N_)) * D;

    // Load Q tile with row swizzle: float4-group g stored at g ^ ((row>>2)&7)
    for (int t = tid; t < 4096; t += 256) {
        int r  = t >> 6;
        int g  = t & 63;
        int sgo = ((g ^ ((r >> 2) & 7)) << 2);
        *(float4*)&Qs[r * 256 + sgo] = *(const float4*)&Qg[r * 256 + (g << 2)];
    }
    if (tid < 64) { m_s[tid] = -1e30f; l_s[tid] = 0.f; }

    float acc[4][16];
#pragma unroll
    for (int i = 0; i < 4; i++)
#pragma unroll
        for (int j = 0; j < 16; j++) acc[i][j] = 0.f;

    __syncthreads();

    const int qs  = ty & 7;   // swizzle key for Q reads (same for rows r0..r0+3)
    const int ksw = tx & 7;   // swizzle key for K reads

    for (int kt = 0; kt < 32; kt++) {
        const float* Kg = Kbase + (long long)(kt * 64) * D;
        const float* Vg = Vbase + (long long)(kt * 64) * D;
        // load K (swizzled) and V (plain)
        for (int t = tid; t < 4096; t += 256) {
            int r = t >> 6;
            int g = t & 63;
            int sgo = ((g ^ ((r >> 2) & 7)) << 2);
            *(float4*)&Ks[r * 256 + sgo]      = *(const float4*)&Kg[r * 256 + (g << 2)];
            *(float4*)&Vs[r * 256 + (g << 2)] = *(const float4*)&Vg[r * 256 + (g << 2)];
        }
        __syncthreads();

        // S = Q K^T * (1/16) for this 64x64 tile; 4x4 per thread
        float s[4][4];
#pragma unroll
        for (int i = 0; i < 4; i++)
#pragma unroll
            for (int j = 0; j < 4; j++) s[i][j] = 0.f;

#pragma unroll 2
        for (int kc = 0; kc < 256; kc += 4) {
            int g  = kc >> 2;
            int qo = ((g ^ qs)  << 2);
            int ko = ((g ^ ksw) << 2);
            float4 qv[4], kv[4];
#pragma unroll
            for (int i = 0; i < 4; i++)
                qv[i] = *(const float4*)&Qs[(r0 + i) * 256 + qo];
#pragma unroll
            for (int j = 0; j < 4; j++)
                kv[j] = *(const float4*)&Ks[(c0 + j) * 256 + ko];
#pragma unroll
            for (int i = 0; i < 4; i++)
#pragma unroll
                for (int j = 0; j < 4; j++)
                    s[i][j] += qv[i].x * kv[j].x + qv[i].y * kv[j].y
                             + qv[i].z * kv[j].z + qv[i].w * kv[j].w;
        }
#pragma unroll
        for (int i = 0; i < 4; i++)
#pragma unroll
            for (int j = 0; j < 4; j++)
                Ps[(r0 + i) * 65 + (c0 + j)] = s[i][j] * 0.0625f;
        __syncthreads();

        // online softmax: 4 threads per row
        {
            int rr = tid >> 2, qq = tid & 3;
            float* prow = Ps + rr * 65 + qq * 16;
            float mx = -1e30f;
#pragma unroll
            for (int i = 0; i < 16; i++) mx = fmaxf(mx, prow[i]);
            mx = fmaxf(mx, __shfl_xor_sync(0xffffffffu, mx, 1));
            mx = fmaxf(mx, __shfl_xor_sync(0xffffffffu, mx, 2));
            float m_old = m_s[rr];
            float m_new = fmaxf(m_old, mx);
            float sum = 0.f;
#pragma unroll
            for (int i = 0; i < 16; i++) {
                float p = __expf(prow[i] - m_new);
                prow[i] = p;
                sum += p;
            }
            sum += __shfl_xor_sync(0xffffffffu, sum, 1);
            sum += __shfl_xor_sync(0xffffffffu, sum, 2);
            if (qq == 0) {
                float f = __expf(m_old - m_new);
                f_s[rr] = f;
                l_s[rr] = l_s[rr] * f + sum;
                m_s[rr] = m_new;
            }
        }
        __syncthreads();

        // rescale accumulators, then acc += P @ V
        {
            float fr[4];
#pragma unroll
            for (int i = 0; i < 4; i++) fr[i] = f_s[r0 + i];
#pragma unroll
            for (int i = 0; i < 4; i++)
#pragma unroll
                for (int j = 0; j < 16; j++) acc[i][j] *= fr[i];
        }
#pragma unroll 2
        for (int nk = 0; nk < 64; nk++) {
            float p[4];
#pragma unroll
            for (int i = 0; i < 4; i++) p[i] = Ps[(r0 + i) * 65 + nk];
#pragma unroll
            for (int j = 0; j < 4; j++) {
                float4 v = *(const float4*)&Vs[nk * 256 + tx * 4 + (j << 6)];
#pragma unroll
                for (int i = 0; i < 4; i++) {
                    acc[i][j * 4 + 0] += p[i] * v.x;
                    acc[i][j * 4 + 1] += p[i] * v.y;
                    acc[i][j * 4 + 2] += p[i] * v.z;
                    acc[i][j * 4 + 3] += p[i] * v.w;
                }
            }
        }
        __syncthreads();
    }

    // normalize and write to concat buffer g_att[b][n][h*256 + d]
    float inv[4];
#pragma unroll
    for (int i = 0; i < 4; i++) inv[i] = 1.0f / l_s[r0 + i];
    const long long obase = ((long long)(b * N_ + q0)) * (NH * D) + h * D;
#pragma unroll
    for (int i = 0; i < 4; i++) {
#pragma unroll
        for (int j = 0; j < 4; j++) {
            float4 o;
            o.x = acc[i][j * 4 + 0] * inv[i];
            o.y = acc[i][j * 4 + 1] * inv[i];
            o.z = acc[i][j * 4 + 2] * inv[i];
            o.w = acc[i][j * 4 + 3] * inv[i];
            *(float4*)&g_att[obase + (long long)(r0 + i) * (NH * D) + tx * 4 + (j << 6)] = o;
        }
    }
}

// ---------------------------------------------------------------------------
// Kernel 3: output projection.  out[m][e] = g_att[m][:] @ W0[:,e] + b0[e]
// grid (6, 128, 1)
// ---------------------------------------------------------------------------
__global__ void __launch_bounds__(256) proj_gemm_kernel(
    const float* __restrict__ W0, const float* __restrict__ b0,
    float* __restrict__ out)
{
    __shared__ float As[8][128];
    __shared__ float Bs[8][128];

    const int m0 = blockIdx.y * 128;
    const int n0 = blockIdx.x * 128;
    const int tid = threadIdx.x;
    const int tx = tid & 15, ty = tid >> 4;
    const int arow = tid >> 1, ak = (tid & 1) << 2;
    const int brow = tid >> 5, bn = (tid & 31) << 2;

    const float* Aptr = g_att + (long long)(m0 + arow) * E + ak;
    const float* Bptr = W0 + brow * E + n0 + bn;

    float c[8][8];
#pragma unroll
    for (int i = 0; i < 8; i++)
#pragma unroll
        for (int j = 0; j < 8; j++) c[i][j] = 0.f;

    for (int k0 = 0; k0 < E; k0 += 8) {
        float4 av  = *(const float4*)(Aptr + k0);
        float4 bv4 = *(const float4*)(Bptr + (long long)k0 * E);
        __syncthreads();
        As[ak + 0][arow] = av.x;
        As[ak + 1][arow] = av.y;
        As[ak + 2][arow] = av.z;
        As[ak + 3][arow] = av.w;
        *(float4*)&Bs[brow][bn] = bv4;
        __syncthreads();
#pragma unroll
        for (int kk = 0; kk < 8; kk++) {
            float a[8], b[8];
            *(float4*)&a[0] = *(float4*)&As[kk][ty * 8];
            *(float4*)&a[4] = *(float4*)&As[kk][ty * 8 + 4];
            *(float4*)&b[0] = *(float4*)&Bs[kk][tx * 8];
            *(float4*)&b[4] = *(float4*)&Bs[kk][tx * 8 + 4];
#pragma unroll
            for (int i = 0; i < 8; i++)
#pragma unroll
                for (int j = 0; j < 8; j++)
                    c[i][j] += a[i] * b[j];
        }
    }

    float bias8[8];
    *(float4*)&bias8[0] = *(const float4*)&b0[n0 + tx * 8];
    *(float4*)&bias8[4] = *(const float4*)&b0[n0 + tx * 8 + 4];

#pragma unroll
    for (int i = 0; i < 8; i++) {
        int m = m0 + ty * 8 + i;
        float* orow = out + (long long)m * E + n0 + tx * 8;
        float4 o0, o1;
        o0.x = c[i][0] + bias8[0]; o0.y = c[i][1] + bias8[1];
        o0.z = c[i][2] + bias8[2]; o0.w = c[i][3] + bias8[3];
        o1.x = c[i][4] + bias8[4]; o1.y = c[i][5] + bias8[5];
        o1.z = c[i][6] + bias8[6]; o1.w = c[i][7] + bias8[7];
        *(float4*)&orow[0] = o0;
        *(float4*)&orow[4] = o1;
    }
}

// ---------------------------------------------------------------------------
extern "C" void kernel_launch(void* const* d_in, const int* in_sizes, int n_in,
                              void* d_out, int out_size)
{
    const float* x  = (const float*)d_in[0];
    const float* Wq = (const float*)d_in[1];
    const float* bq = (const float*)d_in[2];
    const float* Wk = (const float*)d_in[3];
    const float* bk = (const float*)d_in[4];
    const float* Wv = (const float*)d_in[5];
    const float* bv = (const float*)d_in[6];
    const float* W0 = (const float*)d_in[7];
    const float* b0 = (const float*)d_in[8];
    float* out = (float*)d_out;

    qkv_gemm_kernel<<<dim3(2, 128, 9), 256>>>(x, Wq, bq, Wk, bk, Wv, bv);

    cudaFuncSetAttribute(attn_kernel,
                         cudaFuncAttributeMaxDynamicSharedMemorySize,
                         ATTN_SMEM_BYTES);
    attn_kernel<<<dim3(32, NH, B_), 256, ATTN_SMEM_BYTES>>>();

    proj_gemm_kernel<<<dim3(6, 128, 1), 256>>>(W0, b0, out);
}

// round 5
// speedup vs baseline: 3.3553x; 3.3553x over previous
#include <cuda_runtime.h>
#include <cuda_bf16.h>
#include <stdint.h>

#define NH   3
#define D    256
#define E    768
#define B_   8
#define N_   2048
#define M_TOT (B_*N_)     /* 16384 */
#define BH_  (B_*NH)      /* 24    */

// ---------------------------------------------------------------------------
// Scratch (__device__ globals: allocation-guard-safe)
// ---------------------------------------------------------------------------
__device__ __align__(256) __nv_bfloat16 g_Xh[(size_t)M_TOT * E];
__device__ __align__(256) __nv_bfloat16 g_Xl[(size_t)M_TOT * E];
__device__ __align__(256) __nv_bfloat16 g_Wth[(size_t)9 * D * E];   // [th][d][e]
__device__ __align__(256) __nv_bfloat16 g_Wtl[(size_t)9 * D * E];
__device__ __align__(256) __nv_bfloat16 g_W0th[(size_t)E * E];      // [n][k]
__device__ __align__(256) __nv_bfloat16 g_W0tl[(size_t)E * E];
__device__ __align__(256) __nv_bfloat16 g_Qh[(size_t)BH_ * N_ * D];
__device__ __align__(256) __nv_bfloat16 g_Ql[(size_t)BH_ * N_ * D];
__device__ __align__(256) __nv_bfloat16 g_Kh[(size_t)BH_ * N_ * D];
__device__ __align__(256) __nv_bfloat16 g_Kl[(size_t)BH_ * N_ * D];
__device__ __align__(256) __nv_bfloat16 g_Vh[(size_t)BH_ * N_ * D];  // [bh][n][d]
__device__ __align__(256) __nv_bfloat16 g_Vl[(size_t)BH_ * N_ * D];
__device__ __align__(256) float         g_S [(size_t)BH_ * N_ * N_]; // 402 MB
__device__ __align__(256) __nv_bfloat16 g_Ph[(size_t)BH_ * N_ * N_];
__device__ __align__(256) __nv_bfloat16 g_Pl[(size_t)BH_ * N_ * N_];
__device__ __align__(256) __nv_bfloat16 g_atth[(size_t)M_TOT * E];
__device__ __align__(256) __nv_bfloat16 g_attl[(size_t)M_TOT * E];

// ---------------------------------------------------------------------------
// PTX helpers (base-target-safe: cp.async / ldmatrix / mma.sync only)
// ---------------------------------------------------------------------------
__device__ __forceinline__ uint32_t smem_u32(const void* p) {
    uint32_t a;
    asm("{ .reg .u64 t; cvta.to.shared.u64 t, %1; cvt.u32.u64 %0, t; }"
        : "=r"(a) : "l"(p));
    return a;
}

#define CP16(smem, gmem) \
    asm volatile("cp.async.cg.shared.global [%0], [%1], 16;" \
                 :: "r"((uint32_t)(smem)), "l"(gmem) : "memory")
#define CP_COMMIT() asm volatile("cp.async.commit_group;" ::: "memory")
#define CP_WAIT_0() asm volatile("cp.async.wait_group 0;" ::: "memory")
#define CP_WAIT_1() asm volatile("cp.async.wait_group 1;" ::: "memory")

#define LDSM_X4(r, addr) \
    asm volatile("ldmatrix.sync.aligned.m8n8.x4.shared.b16 {%0,%1,%2,%3}, [%4];" \
                 : "=r"((r)[0]), "=r"((r)[1]), "=r"((r)[2]), "=r"((r)[3]) \
                 : "r"(addr))
#define LDSM_X4_T(r, addr) \
    asm volatile("ldmatrix.sync.aligned.m8n8.x4.trans.shared.b16 {%0,%1,%2,%3}, [%4];" \
                 : "=r"((r)[0]), "=r"((r)[1]), "=r"((r)[2]), "=r"((r)[3]) \
                 : "r"(addr))

#define MMA16816(d, a, b0, b1) \
    asm volatile("mma.sync.aligned.m16n8k16.row.col.f32.bf16.bf16.f32 " \
                 "{%0,%1,%2,%3}, {%4,%5,%6,%7}, {%8,%9}, {%0,%1,%2,%3};" \
                 : "+f"((d)[0]), "+f"((d)[1]), "+f"((d)[2]), "+f"((d)[3]) \
                 : "r"((a)[0]), "r"((a)[1]), "r"((a)[2]), "r"((a)[3]), \
                   "r"(b0), "r"(b1))

// ---------------------------------------------------------------------------
// bf16 hi/lo helpers
// ---------------------------------------------------------------------------
__device__ __forceinline__ float bf16f(float a) {
    return __bfloat162float(__float2bfloat16(a));
}
__device__ __forceinline__ uint32_t pack2(float a, float b) {
    __nv_bfloat16 x = __float2bfloat16(a), y = __float2bfloat16(b);
    return (uint32_t)__bfloat16_as_ushort(x) | ((uint32_t)__bfloat16_as_ushort(y) << 16);
}
__device__ __forceinline__ void store_pair_hilo(__nv_bfloat16* dh, __nv_bfloat16* dl,
                                                size_t idx, float v0, float v1) {
    *reinterpret_cast<uint32_t*>(dh + idx) = pack2(v0, v1);
    *reinterpret_cast<uint32_t*>(dl + idx) = pack2(v0 - bf16f(v0), v1 - bf16f(v1));
}

// ---------------------------------------------------------------------------
// GEMM engine: C[128x128] += (Ah+Al)(Bh+Bl)^T  (drop Al*Bl)
// A: [128 rows, Kdim] K-major, row stride = lda.
// B (BT=false): [128 out-cols as rows, Kdim] K-major, row stride ldb.
// B (BT=true) : [Kdim rows, out-cols] (k-major rows), row stride ldb; CTA uses
//               a 128-wide column slice (pointer pre-offset to col0).
// K-chunk = 64 elements. 2-stage cp.async pipeline, 64KB/stage.
// SMEM stage layout: Ah 16K | Al 16K | Bh 16K | Bl 16K.
// ---------------------------------------------------------------------------
#define ST_AL 16384u
#define ST_BH 32768u
#define ST_BL 49152u
#define STAGE_BYTES 65536u
#define GSMEM_BYTES (2 * STAGE_BYTES)

template <bool BT>
__device__ __forceinline__ void ld_stage(
    uint32_t st,
    const __nv_bfloat16* __restrict__ Ah, const __nv_bfloat16* __restrict__ Al,
    const __nv_bfloat16* __restrict__ Bh, const __nv_bfloat16* __restrict__ Bl,
    int lda, int ldb, int k0, int tid)
{
#pragma unroll
    for (int i = 0; i < 4; i++) {                       // A: 128 rows x 8 groups
        int f = tid + i * 256, r = f >> 3, g = f & 7;
        uint32_t sw = (uint32_t)(r * 128 + ((g ^ (r & 7)) << 4));
        CP16(st + sw,         Ah + (size_t)r * lda + k0 + g * 8);
        CP16(st + ST_AL + sw, Al + (size_t)r * lda + k0 + g * 8);
    }
    if (!BT) {
#pragma unroll
        for (int i = 0; i < 4; i++) {                   // B: 128 rows x 8 groups
            int f = tid + i * 256, r = f >> 3, g = f & 7;
            uint32_t sw = (uint32_t)(r * 128 + ((g ^ (r & 7)) << 4));
            CP16(st + ST_BH + sw, Bh + (size_t)r * ldb + k0 + g * 8);
            CP16(st + ST_BL + sw, Bl + (size_t)r * ldb + k0 + g * 8);
        }
    } else {
#pragma unroll
        for (int i = 0; i < 4; i++) {                   // B: 64 k-rows x 16 groups
            int f = tid + i * 256, r = f >> 4, g = f & 15;
            uint32_t sw = (uint32_t)(r * 256 + ((g ^ (r & 7)) << 4));
            CP16(st + ST_BH + sw, Bh + (size_t)(k0 + r) * ldb + g * 8);
            CP16(st + ST_BL + sw, Bl + (size_t)(k0 + r) * ldb + g * 8);
        }
    }
    CP_COMMIT();
}

template <bool BT>
__device__ __forceinline__ void gemm_ml(
    const __nv_bfloat16* Ah, const __nv_bfloat16* Al,
    const __nv_bfloat16* Bh, const __nv_bfloat16* Bl,
    int Kdim, int lda, int ldb, float (&acc)[4][4][4], char* smem)
{
    const uint32_t sb = smem_u32(smem);
    const int tid  = threadIdx.x;
    const int lane = tid & 31;
    const int wid  = tid >> 5;
    const int wm   = wid & 1;        // 2 M-warps (64 rows each)
    const int wn   = wid >> 1;       // 4 N-warps (32 cols each)

    // ldmatrix lane addressing (A, non-trans)
    const int rA  = wm * 64 + (lane & 15);
    const int qa  = lane >> 4;
    const int swA = rA & 7;
    // B non-trans
    const int rB  = wn * 32 + (lane & 7) + ((lane >> 4) << 3);
    const int qb  = (lane >> 3) & 1;
    const int swB = rB & 7;
    // B trans (k-rows)
    const int kB  = (lane & 7) + (((lane >> 3) & 1) << 3);
    const int gB  = (wn * 32 + ((lane >> 4) << 3)) >> 3;  // 16B group of d-col

    const int nc = Kdim >> 6;

    ld_stage<BT>(sb, Ah, Al, Bh, Bl, lda, ldb, 0, tid);

    for (int c = 0; c < nc; c++) {
        uint32_t st = sb + (uint32_t)(c & 1) * STAGE_BYTES;
        if (c + 1 < nc) {
            ld_stage<BT>(sb + (uint32_t)((c + 1) & 1) * STAGE_BYTES,
                         Ah, Al, Bh, Bl, lda, ldb, (c + 1) << 6, tid);
            CP_WAIT_1();
        } else {
            CP_WAIT_0();
        }
        __syncthreads();

        const uint32_t stA = st, stAl = st + ST_AL;
        const uint32_t stB = st + ST_BH, stBl = st + ST_BL;

#pragma unroll
        for (int kk = 0; kk < 4; kk++) {
            uint32_t ah[4][4], al[4][4], bh[2][4], bl[2][4];
            const uint32_t aoff = (uint32_t)(((2 * kk + qa) ^ swA) << 4);
#pragma unroll
            for (int mt = 0; mt < 4; mt++) {
                uint32_t ro = (uint32_t)((rA + mt * 16) * 128) + aoff;
                LDSM_X4(ah[mt], stA  + ro);
                LDSM_X4(al[mt], stAl + ro);
            }
            if (!BT) {
                const uint32_t boff = (uint32_t)(((2 * kk + qb) ^ swB) << 4);
#pragma unroll
                for (int nt2 = 0; nt2 < 2; nt2++) {
                    uint32_t ro = (uint32_t)((rB + nt2 * 16) * 128) + boff;
                    LDSM_X4(bh[nt2], stB  + ro);
                    LDSM_X4(bl[nt2], stBl + ro);
                }
            } else {
                const int k = kk * 16 + kB;
#pragma unroll
                for (int nt2 = 0; nt2 < 2; nt2++) {
                    uint32_t ro = (uint32_t)(k * 256 + (((gB + nt2 * 2) ^ (k & 7)) << 4));
                    LDSM_X4_T(bh[nt2], stB  + ro);
                    LDSM_X4_T(bl[nt2], stBl + ro);
                }
            }
#pragma unroll
            for (int mt = 0; mt < 4; mt++)
#pragma unroll
                for (int nt = 0; nt < 4; nt++) {
                    const int n2 = nt >> 1, hi = (nt & 1) * 2;
                    MMA16816(acc[mt][nt], ah[mt], bh[n2][hi], bh[n2][hi + 1]);
                    MMA16816(acc[mt][nt], ah[mt], bl[n2][hi], bl[n2][hi + 1]);
                    MMA16816(acc[mt][nt], al[mt], bh[n2][hi], bh[n2][hi + 1]);
                }
        }
        __syncthreads();
    }
}

// Per-lane output coordinates: for (mt, nt): rows r0 = wm*64+mt*16+lane/4 and
// r0+8; cols c = wn*32+nt*8+(lane%4)*2 (pair c, c+1).
// acc[mt][nt] = {c0:(r0,c), c1:(r0,c+1), c2:(r0+8,c), c3:(r0+8,c+1)}

// ---------------------------------------------------------------------------
// Conversion kernels
// ---------------------------------------------------------------------------
__global__ void __launch_bounds__(256) convert_x_kernel(const float* __restrict__ x) {
    size_t i = (size_t)blockIdx.x * 256 + threadIdx.x;   // < M_TOT*E/4
    float4 v = reinterpret_cast<const float4*>(x)[i];
    uint2 h, l;
    h.x = pack2(v.x, v.y);  h.y = pack2(v.z, v.w);
    l.x = pack2(v.x - bf16f(v.x), v.y - bf16f(v.y));
    l.y = pack2(v.z - bf16f(v.z), v.w - bf16f(v.w));
    reinterpret_cast<uint2*>(g_Xh)[i] = h;
    reinterpret_cast<uint2*>(g_Xl)[i] = l;
}

__global__ void __launch_bounds__(256) convert_w_kernel(
    const float* __restrict__ Wq, const float* __restrict__ Wk,
    const float* __restrict__ Wv, const float* __restrict__ W0)
{
    size_t i = (size_t)blockIdx.x * 256 + threadIdx.x;   // < 9*D*E + E*E
    if (i < (size_t)9 * D * E) {
        int th = (int)(i / (D * E));
        int r  = (int)(i % (D * E));
        int d  = r / E, e = r % E;
        int t = th / 3, h = th % 3;
        const float* W = (t == 0) ? Wq : (t == 1) ? Wk : Wv;
        float v = W[((size_t)h * E + e) * D + d];
        g_Wth[i] = __float2bfloat16(v);
        g_Wtl[i] = __float2bfloat16(v - bf16f(v));
    } else {
        size_t j = i - (size_t)9 * D * E;                // [n][k]
        int n = (int)(j / E), k = (int)(j % E);
        float v = W0[(size_t)k * E + n];
        g_W0th[j] = __float2bfloat16(v);
        g_W0tl[j] = __float2bfloat16(v - bf16f(v));
    }
}

// ---------------------------------------------------------------------------
// 1) QKV: grid (2, 128, 9).  X @ W(th)^T + bias -> Q/K/V hi-lo, [bh][n][d]
// ---------------------------------------------------------------------------
__global__ void __launch_bounds__(256, 1) qkv_tc_kernel(
    const float* __restrict__ bq, const float* __restrict__ bk,
    const float* __restrict__ bv)
{
    extern __shared__ char smem[];
    const int th = blockIdx.z;
    const int t = th / 3, h = th % 3;
    const int m0 = blockIdx.y * 128;
    const int n0 = blockIdx.x * 128;

    const __nv_bfloat16* Ah = g_Xh + (size_t)m0 * E;
    const __nv_bfloat16* Al = g_Xl + (size_t)m0 * E;
    const __nv_bfloat16* Bh = g_Wth + (size_t)th * D * E + (size_t)n0 * E;
    const __nv_bfloat16* Bl = g_Wtl + (size_t)th * D * E + (size_t)n0 * E;

    float acc[4][4][4] = {};
    gemm_ml<false>(Ah, Al, Bh, Bl, E, E, E, acc, smem);

    const float* bias = ((t == 0) ? bq : (t == 1) ? bk : bv) + h * D;
    __nv_bfloat16* dh = (t == 0) ? g_Qh : (t == 1) ? g_Kh : g_Vh;
    __nv_bfloat16* dl = (t == 0) ? g_Ql : (t == 1) ? g_Kl : g_Vl;

    const int lane = threadIdx.x & 31, wid = threadIdx.x >> 5;
    const int wm = wid & 1, wn = wid >> 1;
#pragma unroll
    for (int mt = 0; mt < 4; mt++) {
        const int r0 = m0 + wm * 64 + mt * 16 + (lane >> 2);
#pragma unroll
        for (int nt = 0; nt < 4; nt++) {
            const int c = n0 + wn * 32 + nt * 8 + (lane & 3) * 2;
            const float bv0 = __ldg(bias + c), bv1 = __ldg(bias + c + 1);
#pragma unroll
            for (int hh = 0; hh < 2; hh++) {
                const int r = r0 + hh * 8;
                const int b = r >> 11, n = r & (N_ - 1);
                const size_t idx = ((size_t)((b * NH + h) * N_ + n)) * D + c;
                store_pair_hilo(dh, dl, idx,
                                acc[mt][nt][2 * hh + 0] + bv0,
                                acc[mt][nt][2 * hh + 1] + bv1);
            }
        }
    }
}

// ---------------------------------------------------------------------------
// 2) S = Q K^T / 16 : grid (16, 16, 24) -> fp32 g_S
// ---------------------------------------------------------------------------
__global__ void __launch_bounds__(256, 1) s_tc_kernel()
{
    extern __shared__ char smem[];
    const int bh = blockIdx.z;
    const int m0 = blockIdx.y * 128;
    const int n0 = blockIdx.x * 128;

    const __nv_bfloat16* Ah = g_Qh + ((size_t)bh * N_ + m0) * D;
    const __nv_bfloat16* Al = g_Ql + ((size_t)bh * N_ + m0) * D;
    const __nv_bfloat16* Bh = g_Kh + ((size_t)bh * N_ + n0) * D;
    const __nv_bfloat16* Bl = g_Kl + ((size_t)bh * N_ + n0) * D;

    float acc[4][4][4] = {};
    gemm_ml<false>(Ah, Al, Bh, Bl, D, D, D, acc, smem);

    const int lane = threadIdx.x & 31, wid = threadIdx.x >> 5;
    const int wm = wid & 1, wn = wid >> 1;
#pragma unroll
    for (int mt = 0; mt < 4; mt++) {
        const int r0 = m0 + wm * 64 + mt * 16 + (lane >> 2);
#pragma unroll
        for (int nt = 0; nt < 4; nt++) {
            const int c = n0 + wn * 32 + nt * 8 + (lane & 3) * 2;
#pragma unroll
            for (int hh = 0; hh < 2; hh++) {
                const int r = r0 + hh * 8;
                float2 o;
                o.x = acc[mt][nt][2 * hh + 0] * 0.0625f;
                o.y = acc[mt][nt][2 * hh + 1] * 0.0625f;
                *reinterpret_cast<float2*>(g_S + ((size_t)bh * N_ + r) * N_ + c) = o;
            }
        }
    }
}

// ---------------------------------------------------------------------------
// 3) softmax rows of S -> P hi/lo.  1 warp per row of 2048.
// ---------------------------------------------------------------------------
__global__ void __launch_bounds__(256) softmax_kernel()
{
    const int warp = threadIdx.x >> 5, lane = threadIdx.x & 31;
    const size_t row = (size_t)blockIdx.x * 8 + warp;
    const float* sr = g_S + row * N_;

    float v[64];
#pragma unroll
    for (int i = 0; i < 16; i++) {
        float4 t = *reinterpret_cast<const float4*>(sr + (i * 32 + lane) * 4);
        v[4*i+0] = t.x; v[4*i+1] = t.y; v[4*i+2] = t.z; v[4*i+3] = t.w;
    }
    float mx = v[0];
#pragma unroll
    for (int j = 1; j < 64; j++) mx = fmaxf(mx, v[j]);
#pragma unroll
    for (int o = 16; o; o >>= 1) mx = fmaxf(mx, __shfl_xor_sync(0xffffffffu, mx, o));
    float sum = 0.f;
#pragma unroll
    for (int j = 0; j < 64; j++) { v[j] = __expf(v[j] - mx); sum += v[j]; }
#pragma unroll
    for (int o = 16; o; o >>= 1) sum += __shfl_xor_sync(0xffffffffu, sum, o);
    const float inv = 1.0f / sum;

    __nv_bfloat16* ph = g_Ph + row * N_;
    __nv_bfloat16* pl = g_Pl + row * N_;
#pragma unroll
    for (int i = 0; i < 16; i++) {
        const int col = (i * 32 + lane) * 4;
        const float p0 = v[4*i+0] * inv, p1 = v[4*i+1] * inv;
        const float p2 = v[4*i+2] * inv, p3 = v[4*i+3] * inv;
        uint2 h, l;
        h.x = pack2(p0, p1); h.y = pack2(p2, p3);
        l.x = pack2(p0 - bf16f(p0), p1 - bf16f(p1));
        l.y = pack2(p2 - bf16f(p2), p3 - bf16f(p3));
        *reinterpret_cast<uint2*>(ph + col) = h;
        *reinterpret_cast<uint2*>(pl + col) = l;
    }
}

// ---------------------------------------------------------------------------
// 4) O = P @ V : grid (2, 16, 24) -> att hi/lo in concat layout [b][n][h*D+d]
//    B operand = V in natural [token][d] layout -> BT (ldmatrix.trans) mode.
// ---------------------------------------------------------------------------
__global__ void __launch_bounds__(256, 1) pv_tc_kernel()
{
    extern __shared__ char smem[];
    const int bh = blockIdx.z;
    const int m0 = blockIdx.y * 128;
    const int n0 = blockIdx.x * 128;     // d-offset
    const int b = bh / 3, h = bh % 3;

    const __nv_bfloat16* Ah = g_Ph + ((size_t)bh * N_ + m0) * N_;
    const __nv_bfloat16* Al = g_Pl + ((size_t)bh * N_ + m0) * N_;
    const __nv_bfloat16* Bh = g_Vh + (size_t)bh * N_ * D + n0;
    const __nv_bfloat16* Bl = g_Vl + (size_t)bh * N_ * D + n0;

    float acc[4][4][4] = {};
    gemm_ml<true>(Ah, Al, Bh, Bl, N_, N_, D, acc, smem);

    const int lane = threadIdx.x & 31, wid = threadIdx.x >> 5;
    const int wm = wid & 1, wn = wid >> 1;
#pragma unroll
    for (int mt = 0; mt < 4; mt++) {
        const int r0 = m0 + wm * 64 + mt * 16 + (lane >> 2);
#pragma unroll
        for (int nt = 0; nt < 4; nt++) {
            const int c = n0 + wn * 32 + nt * 8 + (lane & 3) * 2;
#pragma unroll
            for (int hh = 0; hh < 2; hh++) {
                const int r = r0 + hh * 8;
                const size_t idx = ((size_t)(b * N_ + r)) * E + h * D + c;
                store_pair_hilo(g_atth, g_attl, idx,
                                acc[mt][nt][2 * hh + 0],
                                acc[mt][nt][2 * hh + 1]);
            }
        }
    }
}

// ---------------------------------------------------------------------------
// 5) out = att @ W0 + b0 : grid (6, 128) -> fp32 out
// ---------------------------------------------------------------------------
__global__ void __launch_bounds__(256, 1) proj_tc_kernel(
    const float* __restrict__ b0, float* __restrict__ out)
{
    extern __shared__ char smem[];
    const int m0 = blockIdx.y * 128;
    const int n0 = blockIdx.x * 128;

    const __nv_bfloat16* Ah = g_atth + (size_t)m0 * E;
    const __nv_bfloat16* Al = g_attl + (size_t)m0 * E;
    const __nv_bfloat16* Bh = g_W0th + (size_t)n0 * E;
    const __nv_bfloat16* Bl = g_W0tl + (size_t)n0 * E;

    float acc[4][4][4] = {};
    gemm_ml<false>(Ah, Al, Bh, Bl, E, E, E, acc, smem);

    const int lane = threadIdx.x & 31, wid = threadIdx.x >> 5;
    const int wm = wid & 1, wn = wid >> 1;
#pragma unroll
    for (int mt = 0; mt < 4; mt++) {
        const int r0 = m0 + wm * 64 + mt * 16 + (lane >> 2);
#pragma unroll
        for (int nt = 0; nt < 4; nt++) {
            const int c = n0 + wn * 32 + nt * 8 + (lane & 3) * 2;
            const float bv0 = __ldg(b0 + c), bv1 = __ldg(b0 + c + 1);
#pragma unroll
            for (int hh = 0; hh < 2; hh++) {
                const int r = r0 + hh * 8;
                float2 o;
                o.x = acc[mt][nt][2 * hh + 0] + bv0;
                o.y = acc[mt][nt][2 * hh + 1] + bv1;
                *reinterpret_cast<float2*>(out + (size_t)r * E + c) = o;
            }
        }
    }
}

// ---------------------------------------------------------------------------
extern "C" void kernel_launch(void* const* d_in, const int* in_sizes, int n_in,
                              void* d_out, int out_size)
{
    const float* x  = (const float*)d_in[0];
    const float* Wq = (const float*)d_in[1];
    const float* bq = (const float*)d_in[2];
    const float* Wk = (const float*)d_in[3];
    const float* bk = (const float*)d_in[4];
    const float* Wv = (const float*)d_in[5];
    const float* bv = (const float*)d_in[6];
    const float* W0 = (const float*)d_in[7];
    const float* b0 = (const float*)d_in[8];
    float* out = (float*)d_out;

    cudaFuncSetAttribute(qkv_tc_kernel,  cudaFuncAttributeMaxDynamicSharedMemorySize, GSMEM_BYTES);
    cudaFuncSetAttribute(s_tc_kernel,    cudaFuncAttributeMaxDynamicSharedMemorySize, GSMEM_BYTES);
    cudaFuncSetAttribute(pv_tc_kernel,   cudaFuncAttributeMaxDynamicSharedMemorySize, GSMEM_BYTES);
    cudaFuncSetAttribute(proj_tc_kernel, cudaFuncAttributeMaxDynamicSharedMemorySize, GSMEM_BYTES);

    convert_x_kernel<<<(M_TOT * E / 4) / 256, 256>>>(x);
    convert_w_kernel<<<(9 * D * E + E * E) / 256, 256>>>(Wq, Wk, Wv, W0);

    qkv_tc_kernel<<<dim3(2, 128, 9), 256, GSMEM_BYTES>>>(bq, bk, bv);
    s_tc_kernel<<<dim3(16, 16, BH_), 256, GSMEM_BYTES>>>();
    softmax_kernel<<<(BH_ * N_) / 8, 256>>>();
    pv_tc_kernel<<<dim3(2, 16, BH_), 256, GSMEM_BYTES>>>();
    proj_tc_kernel<<<dim3(6, 128), 256, GSMEM_BYTES>>>(b0, out);
}